// round 7
// baseline (speedup 1.0000x reference)
#include <cuda_runtime.h>
#include <cstdint>

// EdgeFeature: B=4, D=64, N=4096, K=16
// out = [ edge_feature (4,128,4096,16) fp32 ; idx (4,65536) as fp32 ]

#define B_ 4
#define D_ 64
#define N_ 4096
#define K_ 16

// Scratch: ONE batch slab (64 MB) reused across batches -> stays L2-resident
__device__ float g_sq[B_ * N_];                       // 64 KB
__device__ float g_dist[(size_t)N_ * N_];             // 64 MB
__device__ int   g_idx[B_ * N_ * K_];                 // 1 MB

// packed f32x2 FMA: both lanes are independent IEEE fp32 FMAs -> bitwise
// identical to scalar fmaf chains (validated rel_err==0 in an earlier round).
__device__ __forceinline__ void fma2(unsigned long long& c,
                                     unsigned long long a, unsigned long long b) {
    asm("fma.rn.f32x2 %0, %1, %2, %0;" : "+l"(c) : "l"(a), "l"(b));
}

// ---------------------------------------------------------------------------
// 1) squared norms (sequential ascending d, fmaf — matches the GEMM's dot
//    accumulation order so self-distance cancels to exactly 0.0f)
// ---------------------------------------------------------------------------
__global__ void sq_kernel(const float* __restrict__ pc) {
    int gid = blockIdx.x * blockDim.x + threadIdx.x;
    int b = gid >> 12;
    int n = gid & (N_ - 1);
    const float* X = pc + (size_t)b * D_ * N_;
    float acc = 0.0f;
    #pragma unroll
    for (int d = 0; d < D_; d++) {
        float v = X[d * N_ + n];
        acc = fmaf(v, v, acc);
    }
    g_sq[gid] = acc;
}

// ---------------------------------------------------------------------------
// 2) dist = sqrt(max(sq_i + sq_j - 2*dot, 0)) for ONE batch.
//    128x128 tile, 256 threads, 8x8 micro-tile, FFMA2 mainloop.
//    A rows duplicated in smem ({a,a} pairs straight from LDS.128);
//    per-row epilogue keeps register pressure low (no v[8][8], no spills).
// ---------------------------------------------------------------------------
__global__ __launch_bounds__(256, 2) void d2_kernel(const float* __restrict__ pc, int b) {
    __shared__ float As2[16][256];   // As2[d][2i]=As2[d][2i+1]=A[d][i]
    __shared__ float Bs[16][128];
    __shared__ float sqa[128];
    __shared__ float sqb[128];

    int i0 = blockIdx.y * 128;
    int j0 = blockIdx.x * 128;
    const float* X = pc + (size_t)b * D_ * N_;
    int t = threadIdx.x;

    if (t < 128) sqa[t]       = g_sq[b * N_ + i0 + t];
    else         sqb[t - 128] = g_sq[b * N_ + j0 + (t - 128)];

    int r = t >> 4;    // 0..15 row group
    int c = t & 15;    // 0..15 col group

    unsigned long long acc2[8][4];   // [row][col-pair]
    #pragma unroll
    for (int ii = 0; ii < 8; ii++)
        #pragma unroll
        for (int q = 0; q < 4; q++) acc2[ii][q] = 0ull;

    for (int dc = 0; dc < D_; dc += 16) {
        __syncthreads();
        #pragma unroll
        for (int l0 = 0; l0 < 512; l0 += 256) {
            int l  = l0 + t;
            int d  = l >> 5;
            int i4 = (l & 31) << 2;
            float4 va = *(const float4*)&X[(size_t)(dc + d) * N_ + i0 + i4];
            float4 vb = *(const float4*)&X[(size_t)(dc + d) * N_ + j0 + i4];
            *(float4*)&As2[d][i4 * 2]     = make_float4(va.x, va.x, va.y, va.y);
            *(float4*)&As2[d][i4 * 2 + 4] = make_float4(va.z, va.z, va.w, va.w);
            *(float4*)&Bs[d][i4]          = vb;
        }
        __syncthreads();

        #pragma unroll
        for (int d = 0; d < 16; d++) {
            ulonglong2 A0 = *(const ulonglong2*)&As2[d][r * 16];
            ulonglong2 A1 = *(const ulonglong2*)&As2[d][r * 16 + 4];
            ulonglong2 A2 = *(const ulonglong2*)&As2[d][r * 16 + 8];
            ulonglong2 A3 = *(const ulonglong2*)&As2[d][r * 16 + 12];
            ulonglong2 B0 = *(const ulonglong2*)&Bs[d][c * 8];
            ulonglong2 B1 = *(const ulonglong2*)&Bs[d][c * 8 + 4];
            unsigned long long ad[8] = {A0.x, A0.y, A1.x, A1.y, A2.x, A2.y, A3.x, A3.y};
            unsigned long long bp[4] = {B0.x, B0.y, B1.x, B1.y};
            #pragma unroll
            for (int ii = 0; ii < 8; ii++)
                #pragma unroll
                for (int q = 0; q < 4; q++)
                    fma2(acc2[ii][q], ad[ii], bp[q]);
        }
    }

    // per-row epilogue: dist = sqrt(clamp(si+sj-2*dot,0)); 2*acc exact.
    #pragma unroll
    for (int ii = 0; ii < 8; ii++) {
        float si = sqa[r * 8 + ii];
        float v[8];
        #pragma unroll
        for (int q = 0; q < 4; q++) {
            float dx = __uint_as_float((unsigned)acc2[ii][q]);
            float dy = __uint_as_float((unsigned)(acc2[ii][q] >> 32));
            float s0 = si + sqb[c * 8 + 2 * q];
            float s1 = si + sqb[c * 8 + 2 * q + 1];
            v[2 * q]     = sqrtf(fmaxf(s0 - 2.0f * dx, 0.0f));
            v[2 * q + 1] = sqrtf(fmaxf(s1 - 2.0f * dy, 0.0f));
        }
        float* dst = g_dist + ((size_t)(i0 + r * 8 + ii) << 12) + j0 + c * 8;
        *(float4*)&dst[0] = *(float4*)&v[0];
        *(float4*)&dst[4] = *(float4*)&v[4];
    }
}

// ---------------------------------------------------------------------------
// 3) select (proven R6 version), per-batch: threshold-filter, one atomic per
//    warp, exact 17-pass warp argmin on u64 keys (bits<<32)|j == lax.top_k.
// ---------------------------------------------------------------------------
__global__ __launch_bounds__(256) void select_kernel(float* __restrict__ out_idx_f, int b) {
    __shared__ unsigned long long buf[4096];
    __shared__ float wtau[8];
    __shared__ int cnt;

    int i   = blockIdx.x;                     // row within batch
    int row = b * N_ + i;
    const float* src = g_dist + (size_t)i * N_;
    int t = threadIdx.x;
    int lane = t & 31, w = t >> 5;
    unsigned lmask_lt = (1u << lane) - 1u;

    if (t == 0) cnt = 0;

    float4 vv[4];
    #pragma unroll
    for (int u = 0; u < 4; u++)
        vv[u] = ((const float4*)src)[128 * w + lane + 32 * u];

    float mn;
    {
        float m0 = fminf(fminf(vv[0].x, vv[0].y), fminf(vv[0].z, vv[0].w));
        float m1 = fminf(fminf(vv[1].x, vv[1].y), fminf(vv[1].z, vv[1].w));
        float m2 = fminf(fminf(vv[2].x, vv[2].y), fminf(vv[2].z, vv[2].w));
        float m3 = fminf(fminf(vv[3].x, vv[3].y), fminf(vv[3].z, vv[3].w));
        mn = fminf(fminf(m0, m1), fminf(m2, m3));
    }

    float x = mn;
    #pragma unroll
    for (int k = 2; k <= 32; k <<= 1) {
        #pragma unroll
        for (int j2 = k >> 1; j2 > 0; j2 >>= 1) {
            float other = __shfl_xor_sync(0xffffffffu, x, j2);
            bool up    = ((lane & k) == 0);
            bool small = ((lane & j2) == 0);
            x = (small == up) ? fminf(x, other) : fmaxf(x, other);
        }
    }
    float tau_w = __shfl_sync(0xffffffffu, x, K_);
    if (lane == 0) wtau[w] = tau_w;
    __syncthreads();
    float tau = wtau[0];
    #pragma unroll
    for (int q = 1; q < 8; q++) tau = fminf(tau, wtau[q]);

    float    val[16];
    unsigned msk[16];
    int tot = 0;
    #pragma unroll
    for (int u = 0; u < 4; u++) {
        val[u * 4 + 0] = vv[u].x; val[u * 4 + 1] = vv[u].y;
        val[u * 4 + 2] = vv[u].z; val[u * 4 + 3] = vv[u].w;
    }
    #pragma unroll
    for (int e = 0; e < 16; e++) {
        msk[e] = __ballot_sync(0xffffffffu, val[e] <= tau);
        tot += __popc(msk[e]);
    }
    int wbase = 0;
    if (lane == 0) wbase = atomicAdd(&cnt, tot);
    wbase = __shfl_sync(0xffffffffu, wbase, 0);
    int off = 0;
    #pragma unroll
    for (int e = 0; e < 16; e++) {
        if (val[e] <= tau) {
            int j = (128 * w + lane + 32 * (e >> 2)) * 4 + (e & 3);
            buf[wbase + off + __popc(msk[e] & lmask_lt)] =
                ((unsigned long long)__float_as_uint(val[e]) << 32) | (unsigned)j;
        }
        off += __popc(msk[e]);
    }
    __syncthreads();

    if (w == 0) {
        int n = cnt;
        for (int p = 0; p <= K_; p++) {
            unsigned long long m = 0xFFFFFFFFFFFFFFFFull;
            for (int q = lane; q < n; q += 32) m = (buf[q] < m) ? buf[q] : m;
            #pragma unroll
            for (int o2 = 16; o2; o2 >>= 1) {
                unsigned long long o = __shfl_xor_sync(0xffffffffu, m, o2);
                m = (o < m) ? o : m;
            }
            for (int q = lane; q < n; q += 32)
                if (buf[q] == m) buf[q] = 0xFFFFFFFFFFFFFFFFull;
            if (lane == 0 && p > 0) {
                int j = (int)(m & 0xFFFFFFFFu);
                g_idx[row * K_ + (p - 1)]     = j;
                out_idx_f[row * K_ + (p - 1)] = (float)j;
            }
        }
    }
}

// ---------------------------------------------------------------------------
// 4) gather v3 (proven 38us): smem-row gather. Block = (b, channel, octant).
// ---------------------------------------------------------------------------
__global__ __launch_bounds__(256) void gather_kernel(const float* __restrict__ pc,
                                                     float* __restrict__ out) {
    __shared__ float rowv[N_];

    int blk = blockIdx.x;            // 2048 blocks: b(2) | c(6) | s(3)
    int s   = blk & 7;
    int c   = (blk >> 3) & 63;
    int b   = blk >> 9;
    int t   = threadIdx.x;
    const float* src = pc + ((size_t)b * D_ + c) * N_;

    #pragma unroll
    for (int q = 0; q < 4; q++)
        ((float4*)rowv)[t + q * 256] = ((const float4*)src)[t + q * 256];
    __syncthreads();

    int n0 = s * 512;
    const int* idxp = g_idx + ((size_t)b * N_ + n0) * K_;
    size_t obase = (size_t)b * 2 * D_ * N_ * K_ + ((size_t)c * N_ + n0) * K_;
    float* oc = out + obase;
    float* on = out + obase + (size_t)D_ * N_ * K_;

    #pragma unroll 4
    for (int it = 0; it < 32; it++) {
        int l = t + it * 256;
        int n = l >> 4;
        int j = idxp[l];
        float ce = rowv[n0 + n];
        float nb = rowv[j];
        oc[l] = ce;
        on[l] = nb - ce;
    }
}

// ---------------------------------------------------------------------------
extern "C" void kernel_launch(void* const* d_in, const int* in_sizes, int n_in,
                              void* d_out, int out_size) {
    const float* pc = (const float*)d_in[0];
    float* out = (float*)d_out;
    float* out_idx = out + (size_t)B_ * 2 * D_ * N_ * K_;

    sq_kernel<<<(B_ * N_) / 256, 256>>>(pc);
    for (int b = 0; b < B_; b++) {
        dim3 gg(N_ / 128, N_ / 128, 1);
        d2_kernel<<<gg, 256>>>(pc, b);          // 64 MB slab, L2-resident
        select_kernel<<<N_, 256>>>(out_idx, b); // reads slab from L2
    }
    gather_kernel<<<B_ * D_ * 8, 256>>>(pc, out);
}

// round 8
// speedup vs baseline: 1.0941x; 1.0941x over previous
#include <cuda_runtime.h>
#include <cstdint>

// EdgeFeature: B=4, D=64, N=4096, K=16
// out = [ edge_feature (4,128,4096,16) fp32 ; idx (4,65536) as fp32 ]

#define B_ 4
#define D_ 64
#define N_ 4096
#define K_ 16

// Scratch (static __device__ — no allocations allowed in kernel_launch)
__device__ float g_sq[B_ * N_];                       // 64 KB
__device__ float g_dist[(size_t)B_ * N_ * N_];        // 256 MB
__device__ int   g_idx[B_ * N_ * K_];                 // 1 MB

// packed f32x2 FMA: both lanes are independent IEEE fp32 FMAs -> bitwise
// identical to scalar fmaf chains (validated rel_err==0 across rounds).
__device__ __forceinline__ void fma2(unsigned long long& c,
                                     unsigned long long a, unsigned long long b) {
    asm("fma.rn.f32x2 %0, %1, %2, %0;" : "+l"(c) : "l"(a), "l"(b));
}

// ---------------------------------------------------------------------------
// 1) squared norms (sequential ascending d, fmaf — matches the GEMM's dot
//    accumulation order so self-distance cancels to exactly 0.0f)
// ---------------------------------------------------------------------------
__global__ void sq_kernel(const float* __restrict__ pc) {
    int gid = blockIdx.x * blockDim.x + threadIdx.x;
    int b = gid >> 12;
    int n = gid & (N_ - 1);
    const float* X = pc + (size_t)b * D_ * N_;
    float acc = 0.0f;
    #pragma unroll
    for (int d = 0; d < D_; d++) {
        float v = X[d * N_ + n];
        acc = fmaf(v, v, acc);
    }
    g_sq[gid] = acc;
}

// ---------------------------------------------------------------------------
// 2) dist = sqrt(max(sq_i + sq_j - 2*dot, 0)). FFMA2 mainloop (measured
//    69.8us/batch in R7). Single launch, grid (32,32,4) to kill launch tails.
//    A rows duplicated in smem ({a,a} pairs straight from LDS.128).
// ---------------------------------------------------------------------------
__global__ __launch_bounds__(256, 2) void d2_kernel(const float* __restrict__ pc) {
    __shared__ float As2[16][256];   // As2[d][2i]=As2[d][2i+1]=A[d][i]
    __shared__ float Bs[16][128];
    __shared__ float sqa[128];
    __shared__ float sqb[128];

    int b  = blockIdx.z;
    int i0 = blockIdx.y * 128;
    int j0 = blockIdx.x * 128;
    const float* X = pc + (size_t)b * D_ * N_;
    int t = threadIdx.x;

    if (t < 128) sqa[t]       = g_sq[b * N_ + i0 + t];
    else         sqb[t - 128] = g_sq[b * N_ + j0 + (t - 128)];

    int r = t >> 4;    // 0..15 row group
    int c = t & 15;    // 0..15 col group

    unsigned long long acc2[8][4];   // [row][col-pair]
    #pragma unroll
    for (int ii = 0; ii < 8; ii++)
        #pragma unroll
        for (int q = 0; q < 4; q++) acc2[ii][q] = 0ull;

    for (int dc = 0; dc < D_; dc += 16) {
        __syncthreads();
        #pragma unroll
        for (int l0 = 0; l0 < 512; l0 += 256) {
            int l  = l0 + t;
            int d  = l >> 5;
            int i4 = (l & 31) << 2;
            float4 va = *(const float4*)&X[(size_t)(dc + d) * N_ + i0 + i4];
            float4 vb = *(const float4*)&X[(size_t)(dc + d) * N_ + j0 + i4];
            *(float4*)&As2[d][i4 * 2]     = make_float4(va.x, va.x, va.y, va.y);
            *(float4*)&As2[d][i4 * 2 + 4] = make_float4(va.z, va.z, va.w, va.w);
            *(float4*)&Bs[d][i4]          = vb;
        }
        __syncthreads();

        #pragma unroll
        for (int d = 0; d < 16; d++) {
            ulonglong2 A0 = *(const ulonglong2*)&As2[d][r * 16];
            ulonglong2 A1 = *(const ulonglong2*)&As2[d][r * 16 + 4];
            ulonglong2 A2 = *(const ulonglong2*)&As2[d][r * 16 + 8];
            ulonglong2 A3 = *(const ulonglong2*)&As2[d][r * 16 + 12];
            ulonglong2 B0 = *(const ulonglong2*)&Bs[d][c * 8];
            ulonglong2 B1 = *(const ulonglong2*)&Bs[d][c * 8 + 4];
            unsigned long long ad[8] = {A0.x, A0.y, A1.x, A1.y, A2.x, A2.y, A3.x, A3.y};
            unsigned long long bp[4] = {B0.x, B0.y, B1.x, B1.y};
            #pragma unroll
            for (int ii = 0; ii < 8; ii++)
                #pragma unroll
                for (int q = 0; q < 4; q++)
                    fma2(acc2[ii][q], ad[ii], bp[q]);
        }
    }

    // per-row epilogue: dist = sqrt(clamp(si+sj-2*dot,0)); 2*acc exact.
    #pragma unroll
    for (int ii = 0; ii < 8; ii++) {
        float si = sqa[r * 8 + ii];
        float v[8];
        #pragma unroll
        for (int q = 0; q < 4; q++) {
            float dx = __uint_as_float((unsigned)acc2[ii][q]);
            float dy = __uint_as_float((unsigned)(acc2[ii][q] >> 32));
            float s0 = si + sqb[c * 8 + 2 * q];
            float s1 = si + sqb[c * 8 + 2 * q + 1];
            v[2 * q]     = sqrtf(fmaxf(s0 - 2.0f * dx, 0.0f));
            v[2 * q + 1] = sqrtf(fmaxf(s1 - 2.0f * dy, 0.0f));
        }
        float* dst = g_dist + ((size_t)(b * N_ + i0 + r * 8 + ii) << 12) + j0 + c * 8;
        *(float4*)&dst[0] = *(float4*)&v[0];
        *(float4*)&dst[4] = *(float4*)&v[4];
    }
}

// ---------------------------------------------------------------------------
// 3) select — EXACT R6 configuration: single launch, 16384 blocks, DRAM
//    streaming at full MLP. Threshold-filter (warp bitonic of lane-minima),
//    one atomic per warp, exact 17-pass warp argmin on u64 keys
//    (bits<<32)|j == lax.top_k order.
// ---------------------------------------------------------------------------
__global__ __launch_bounds__(256) void select_kernel(float* __restrict__ out_idx_f) {
    __shared__ unsigned long long buf[4096];
    __shared__ float wtau[8];
    __shared__ int cnt;

    int row = blockIdx.x;                      // b*4096 + i
    const float* src = g_dist + (size_t)row * N_;
    int t = threadIdx.x;
    int lane = t & 31, w = t >> 5;
    unsigned lmask_lt = (1u << lane) - 1u;

    if (t == 0) cnt = 0;

    // warp w owns cols [512w, 512w+512): lane reads 4 coalesced float4s
    float4 vv[4];
    #pragma unroll
    for (int u = 0; u < 4; u++)
        vv[u] = ((const float4*)src)[128 * w + lane + 32 * u];

    float mn;
    {
        float m0 = fminf(fminf(vv[0].x, vv[0].y), fminf(vv[0].z, vv[0].w));
        float m1 = fminf(fminf(vv[1].x, vv[1].y), fminf(vv[1].z, vv[1].w));
        float m2 = fminf(fminf(vv[2].x, vv[2].y), fminf(vv[2].z, vv[2].w));
        float m3 = fminf(fminf(vv[3].x, vv[3].y), fminf(vv[3].z, vv[3].w));
        mn = fminf(fminf(m0, m1), fminf(m2, m3));
    }

    // bitonic sort of lane minima across the warp
    float x = mn;
    #pragma unroll
    for (int k = 2; k <= 32; k <<= 1) {
        #pragma unroll
        for (int j2 = k >> 1; j2 > 0; j2 >>= 1) {
            float other = __shfl_xor_sync(0xffffffffu, x, j2);
            bool up    = ((lane & k) == 0);
            bool small = ((lane & j2) == 0);
            x = (small == up) ? fminf(x, other) : fmaxf(x, other);
        }
    }
    float tau_w = __shfl_sync(0xffffffffu, x, K_);   // 17th smallest lane-min
    if (lane == 0) wtau[w] = tau_w;
    __syncthreads();
    float tau = wtau[0];
    #pragma unroll
    for (int q = 1; q < 8; q++) tau = fminf(tau, wtau[q]);

    // filter + warp-aggregated compaction (one atomic per warp)
    float    val[16];
    unsigned msk[16];
    int tot = 0;
    #pragma unroll
    for (int u = 0; u < 4; u++) {
        val[u * 4 + 0] = vv[u].x; val[u * 4 + 1] = vv[u].y;
        val[u * 4 + 2] = vv[u].z; val[u * 4 + 3] = vv[u].w;
    }
    #pragma unroll
    for (int e = 0; e < 16; e++) {
        msk[e] = __ballot_sync(0xffffffffu, val[e] <= tau);
        tot += __popc(msk[e]);
    }
    int wbase = 0;
    if (lane == 0) wbase = atomicAdd(&cnt, tot);
    wbase = __shfl_sync(0xffffffffu, wbase, 0);
    int off = 0;
    #pragma unroll
    for (int e = 0; e < 16; e++) {
        if (val[e] <= tau) {
            int j = (128 * w + lane + 32 * (e >> 2)) * 4 + (e & 3);
            buf[wbase + off + __popc(msk[e] & lmask_lt)] =
                ((unsigned long long)__float_as_uint(val[e]) << 32) | (unsigned)j;
        }
        off += __popc(msk[e]);
    }
    __syncthreads();

    // exact top-17 on the candidate set (warp 0; n typically ~100-300)
    if (w == 0) {
        int n = cnt;
        for (int p = 0; p <= K_; p++) {
            unsigned long long m = 0xFFFFFFFFFFFFFFFFull;
            for (int q = lane; q < n; q += 32) m = (buf[q] < m) ? buf[q] : m;
            #pragma unroll
            for (int o2 = 16; o2; o2 >>= 1) {
                unsigned long long o = __shfl_xor_sync(0xffffffffu, m, o2);
                m = (o < m) ? o : m;
            }
            for (int q = lane; q < n; q += 32)
                if (buf[q] == m) buf[q] = 0xFFFFFFFFFFFFFFFFull;
            if (lane == 0 && p > 0) {
                int j = (int)(m & 0xFFFFFFFFu);
                g_idx[row * K_ + (p - 1)]     = j;
                out_idx_f[row * K_ + (p - 1)] = (float)j;
            }
        }
    }
}

// ---------------------------------------------------------------------------
// 4) gather v3 (measured 38us): smem-row gather. Block = (b, channel, octant).
// ---------------------------------------------------------------------------
__global__ __launch_bounds__(256) void gather_kernel(const float* __restrict__ pc,
                                                     float* __restrict__ out) {
    __shared__ float rowv[N_];

    int blk = blockIdx.x;            // 2048 blocks: b(2) | c(6) | s(3)
    int s   = blk & 7;
    int c   = (blk >> 3) & 63;
    int b   = blk >> 9;
    int t   = threadIdx.x;
    const float* src = pc + ((size_t)b * D_ + c) * N_;

    #pragma unroll
    for (int q = 0; q < 4; q++)
        ((float4*)rowv)[t + q * 256] = ((const float4*)src)[t + q * 256];
    __syncthreads();

    int n0 = s * 512;
    const int* idxp = g_idx + ((size_t)b * N_ + n0) * K_;
    size_t obase = (size_t)b * 2 * D_ * N_ * K_ + ((size_t)c * N_ + n0) * K_;
    float* oc = out + obase;
    float* on = out + obase + (size_t)D_ * N_ * K_;

    #pragma unroll 4
    for (int it = 0; it < 32; it++) {
        int l = t + it * 256;
        int n = l >> 4;
        int j = idxp[l];
        float ce = rowv[n0 + n];
        float nb = rowv[j];
        oc[l] = ce;
        on[l] = nb - ce;
    }
}

// ---------------------------------------------------------------------------
extern "C" void kernel_launch(void* const* d_in, const int* in_sizes, int n_in,
                              void* d_out, int out_size) {
    const float* pc = (const float*)d_in[0];
    float* out = (float*)d_out;
    float* out_idx = out + (size_t)B_ * 2 * D_ * N_ * K_;

    sq_kernel<<<(B_ * N_) / 256, 256>>>(pc);
    dim3 gg(N_ / 128, N_ / 128, B_);
    d2_kernel<<<gg, 256>>>(pc);
    select_kernel<<<B_ * N_, 256>>>(out_idx);
    gather_kernel<<<B_ * D_ * 8, 256>>>(pc, out);
}

// round 9
// speedup vs baseline: 1.1739x; 1.0729x over previous
#include <cuda_runtime.h>
#include <cstdint>

// EdgeFeature: B=4, D=64, N=4096, K=16
// out = [ edge_feature (4,128,4096,16) fp32 ; idx (4,65536) as fp32 ]

#define B_ 4
#define D_ 64
#define N_ 4096
#define K_ 16

// Scratch (static __device__ — no allocations allowed in kernel_launch)
__device__ float g_sq[B_ * N_];                       // 64 KB
__device__ float g_dist[(size_t)B_ * N_ * N_];        // 256 MB
__device__ int   g_idx[B_ * N_ * K_];                 // 1 MB

// packed f32x2 FMA: both lanes are independent IEEE fp32 FMAs -> bitwise
// identical to scalar fmaf chains (validated rel_err==0 across rounds).
__device__ __forceinline__ void fma2(unsigned long long& c,
                                     unsigned long long a, unsigned long long b) {
    asm("fma.rn.f32x2 %0, %1, %2, %0;" : "+l"(c) : "l"(a), "l"(b));
}

// ---------------------------------------------------------------------------
// 1) squared norms (sequential ascending d, fmaf — matches the GEMM's dot
//    accumulation order so self-distance cancels to exactly 0.0f)
// ---------------------------------------------------------------------------
__global__ void sq_kernel(const float* __restrict__ pc) {
    int gid = blockIdx.x * blockDim.x + threadIdx.x;
    int b = gid >> 12;
    int n = gid & (N_ - 1);
    const float* X = pc + (size_t)b * D_ * N_;
    float acc = 0.0f;
    #pragma unroll
    for (int d = 0; d < D_; d++) {
        float v = X[d * N_ + n];
        acc = fmaf(v, v, acc);
    }
    g_sq[gid] = acc;
}

// ---------------------------------------------------------------------------
// 2) dist = sqrt(max(sq_i + sq_j - 2*dot, 0)). FFMA2 mainloop, v2:
//    NO smem A-duplication (that made the LDS crossbar the bottleneck:
//    96B/thread/d-step > FMA budget). A loaded plain (2x LDS.128), {a,a}
//    pairs built in registers via mov.b64 on the ALU pipe (idle headroom).
//    Per-SM per-d-step: LDS 256cyc == FMA 256cyc, balanced.
//    K-chunk widened to 32 -> only 2 chunk boundaries.
// ---------------------------------------------------------------------------
__global__ __launch_bounds__(256, 2) void d2_kernel(const float* __restrict__ pc) {
    __shared__ float As[32][128];
    __shared__ float Bs[32][128];
    __shared__ float sqa[128];
    __shared__ float sqb[128];

    int b  = blockIdx.z;
    int i0 = blockIdx.y * 128;
    int j0 = blockIdx.x * 128;
    const float* X = pc + (size_t)b * D_ * N_;
    int t = threadIdx.x;

    if (t < 128) sqa[t]       = g_sq[b * N_ + i0 + t];
    else         sqb[t - 128] = g_sq[b * N_ + j0 + (t - 128)];

    int r = t >> 4;    // 0..15 row group
    int c = t & 15;    // 0..15 col group

    unsigned long long acc2[8][4];   // [row][col-pair]
    #pragma unroll
    for (int ii = 0; ii < 8; ii++)
        #pragma unroll
        for (int q = 0; q < 4; q++) acc2[ii][q] = 0ull;

    for (int dc = 0; dc < D_; dc += 32) {
        __syncthreads();
        for (int l = t; l < 1024; l += 256) {
            int d  = l >> 5;
            int i4 = (l & 31) << 2;
            *(float4*)&As[d][i4] = *(const float4*)&X[(size_t)(dc + d) * N_ + i0 + i4];
            *(float4*)&Bs[d][i4] = *(const float4*)&X[(size_t)(dc + d) * N_ + j0 + i4];
        }
        __syncthreads();

        #pragma unroll 8
        for (int d = 0; d < 32; d++) {
            float af[8];
            *(float4*)&af[0] = *(float4*)&As[d][r * 8];
            *(float4*)&af[4] = *(float4*)&As[d][r * 8 + 4];
            ulonglong2 B0 = *(const ulonglong2*)&Bs[d][c * 8];
            ulonglong2 B1 = *(const ulonglong2*)&Bs[d][c * 8 + 4];
            unsigned long long bp[4] = {B0.x, B0.y, B1.x, B1.y};
            unsigned long long ap[8];
            #pragma unroll
            for (int ii = 0; ii < 8; ii++)
                asm("mov.b64 %0, {%1, %1};" : "=l"(ap[ii]) : "f"(af[ii]));
            #pragma unroll
            for (int ii = 0; ii < 8; ii++)
                #pragma unroll
                for (int q = 0; q < 4; q++)
                    fma2(acc2[ii][q], ap[ii], bp[q]);
        }
    }

    // per-row epilogue: dist = sqrt(clamp(si+sj-2*dot,0)); 2*acc exact.
    #pragma unroll
    for (int ii = 0; ii < 8; ii++) {
        float si = sqa[r * 8 + ii];
        float v[8];
        #pragma unroll
        for (int q = 0; q < 4; q++) {
            float dx = __uint_as_float((unsigned)acc2[ii][q]);
            float dy = __uint_as_float((unsigned)(acc2[ii][q] >> 32));
            float s0 = si + sqb[c * 8 + 2 * q];
            float s1 = si + sqb[c * 8 + 2 * q + 1];
            v[2 * q]     = sqrtf(fmaxf(s0 - 2.0f * dx, 0.0f));
            v[2 * q + 1] = sqrtf(fmaxf(s1 - 2.0f * dy, 0.0f));
        }
        float* dst = g_dist + ((size_t)(b * N_ + i0 + r * 8 + ii) << 12) + j0 + c * 8;
        *(float4*)&dst[0] = *(float4*)&v[0];
        *(float4*)&dst[4] = *(float4*)&v[4];
    }
}

// ---------------------------------------------------------------------------
// 3) select — proven R6/R8 configuration (measured-consistent ~116us):
//    single launch, 16384 blocks. Threshold-filter (warp bitonic of lane
//    minima), one atomic per warp, exact 17-pass warp argmin on u64 keys
//    (bits<<32)|j == lax.top_k order.
// ---------------------------------------------------------------------------
__global__ __launch_bounds__(256) void select_kernel(float* __restrict__ out_idx_f) {
    __shared__ unsigned long long buf[4096];
    __shared__ float wtau[8];
    __shared__ int cnt;

    int row = blockIdx.x;                      // b*4096 + i
    const float* src = g_dist + (size_t)row * N_;
    int t = threadIdx.x;
    int lane = t & 31, w = t >> 5;
    unsigned lmask_lt = (1u << lane) - 1u;

    if (t == 0) cnt = 0;

    float4 vv[4];
    #pragma unroll
    for (int u = 0; u < 4; u++)
        vv[u] = ((const float4*)src)[128 * w + lane + 32 * u];

    float mn;
    {
        float m0 = fminf(fminf(vv[0].x, vv[0].y), fminf(vv[0].z, vv[0].w));
        float m1 = fminf(fminf(vv[1].x, vv[1].y), fminf(vv[1].z, vv[1].w));
        float m2 = fminf(fminf(vv[2].x, vv[2].y), fminf(vv[2].z, vv[2].w));
        float m3 = fminf(fminf(vv[3].x, vv[3].y), fminf(vv[3].z, vv[3].w));
        mn = fminf(fminf(m0, m1), fminf(m2, m3));
    }

    float x = mn;
    #pragma unroll
    for (int k = 2; k <= 32; k <<= 1) {
        #pragma unroll
        for (int j2 = k >> 1; j2 > 0; j2 >>= 1) {
            float other = __shfl_xor_sync(0xffffffffu, x, j2);
            bool up    = ((lane & k) == 0);
            bool small = ((lane & j2) == 0);
            x = (small == up) ? fminf(x, other) : fmaxf(x, other);
        }
    }
    float tau_w = __shfl_sync(0xffffffffu, x, K_);
    if (lane == 0) wtau[w] = tau_w;
    __syncthreads();
    float tau = wtau[0];
    #pragma unroll
    for (int q = 1; q < 8; q++) tau = fminf(tau, wtau[q]);

    float    val[16];
    unsigned msk[16];
    int tot = 0;
    #pragma unroll
    for (int u = 0; u < 4; u++) {
        val[u * 4 + 0] = vv[u].x; val[u * 4 + 1] = vv[u].y;
        val[u * 4 + 2] = vv[u].z; val[u * 4 + 3] = vv[u].w;
    }
    #pragma unroll
    for (int e = 0; e < 16; e++) {
        msk[e] = __ballot_sync(0xffffffffu, val[e] <= tau);
        tot += __popc(msk[e]);
    }
    int wbase = 0;
    if (lane == 0) wbase = atomicAdd(&cnt, tot);
    wbase = __shfl_sync(0xffffffffu, wbase, 0);
    int off = 0;
    #pragma unroll
    for (int e = 0; e < 16; e++) {
        if (val[e] <= tau) {
            int j = (128 * w + lane + 32 * (e >> 2)) * 4 + (e & 3);
            buf[wbase + off + __popc(msk[e] & lmask_lt)] =
                ((unsigned long long)__float_as_uint(val[e]) << 32) | (unsigned)j;
        }
        off += __popc(msk[e]);
    }
    __syncthreads();

    if (w == 0) {
        int n = cnt;
        for (int p = 0; p <= K_; p++) {
            unsigned long long m = 0xFFFFFFFFFFFFFFFFull;
            for (int q = lane; q < n; q += 32) m = (buf[q] < m) ? buf[q] : m;
            #pragma unroll
            for (int o2 = 16; o2; o2 >>= 1) {
                unsigned long long o = __shfl_xor_sync(0xffffffffu, m, o2);
                m = (o < m) ? o : m;
            }
            for (int q = lane; q < n; q += 32)
                if (buf[q] == m) buf[q] = 0xFFFFFFFFFFFFFFFFull;
            if (lane == 0 && p > 0) {
                int j = (int)(m & 0xFFFFFFFFu);
                g_idx[row * K_ + (p - 1)]     = j;
                out_idx_f[row * K_ + (p - 1)] = (float)j;
            }
        }
    }
}

// ---------------------------------------------------------------------------
// 4) gather v3 (measured 38us): smem-row gather. Block = (b, channel, octant).
// ---------------------------------------------------------------------------
__global__ __launch_bounds__(256) void gather_kernel(const float* __restrict__ pc,
                                                     float* __restrict__ out) {
    __shared__ float rowv[N_];

    int blk = blockIdx.x;            // 2048 blocks: b(2) | c(6) | s(3)
    int s   = blk & 7;
    int c   = (blk >> 3) & 63;
    int b   = blk >> 9;
    int t   = threadIdx.x;
    const float* src = pc + ((size_t)b * D_ + c) * N_;

    #pragma unroll
    for (int q = 0; q < 4; q++)
        ((float4*)rowv)[t + q * 256] = ((const float4*)src)[t + q * 256];
    __syncthreads();

    int n0 = s * 512;
    const int* idxp = g_idx + ((size_t)b * N_ + n0) * K_;
    size_t obase = (size_t)b * 2 * D_ * N_ * K_ + ((size_t)c * N_ + n0) * K_;
    float* oc = out + obase;
    float* on = out + obase + (size_t)D_ * N_ * K_;

    #pragma unroll 4
    for (int it = 0; it < 32; it++) {
        int l = t + it * 256;
        int n = l >> 4;
        int j = idxp[l];
        float ce = rowv[n0 + n];
        float nb = rowv[j];
        oc[l] = ce;
        on[l] = nb - ce;
    }
}

// ---------------------------------------------------------------------------
extern "C" void kernel_launch(void* const* d_in, const int* in_sizes, int n_in,
                              void* d_out, int out_size) {
    const float* pc = (const float*)d_in[0];
    float* out = (float*)d_out;
    float* out_idx = out + (size_t)B_ * 2 * D_ * N_ * K_;

    sq_kernel<<<(B_ * N_) / 256, 256>>>(pc);
    dim3 gg(N_ / 128, N_ / 128, B_);
    d2_kernel<<<gg, 256>>>(pc);
    select_kernel<<<B_ * N_, 256>>>(out_idx);
    gather_kernel<<<B_ * D_ * 8, 256>>>(pc, out);
}

// round 11
// speedup vs baseline: 1.2768x; 1.0877x over previous
#include <cuda_runtime.h>
#include <cstdint>

// EdgeFeature: B=4, D=64, N=4096, K=16
// out = [ edge_feature (4,128,4096,16) fp32 ; idx (4,65536) as fp32 ]

#define B_ 4
#define D_ 64
#define N_ 4096
#define K_ 16

// Scratch (static __device__ — no allocations allowed in kernel_launch)
__device__ float g_sq[B_ * N_];                       // 64 KB
__device__ float g_dist[(size_t)B_ * N_ * N_];        // 256 MB
__device__ int   g_idx[B_ * N_ * K_];                 // 1 MB

// packed f32x2 FMA: both lanes are independent IEEE fp32 FMAs -> bitwise
// identical to scalar fmaf chains (validated rel_err==0 across rounds).
__device__ __forceinline__ void fma2(unsigned long long& c,
                                     unsigned long long a, unsigned long long b) {
    asm("fma.rn.f32x2 %0, %1, %2, %0;" : "+l"(c) : "l"(a), "l"(b));
}

// ---------------------------------------------------------------------------
// 1) squared norms (sequential ascending d, fmaf — matches the GEMM's dot
//    accumulation order so self-distance cancels to exactly 0.0f)
// ---------------------------------------------------------------------------
__global__ void sq_kernel(const float* __restrict__ pc) {
    int gid = blockIdx.x * blockDim.x + threadIdx.x;
    int b = gid >> 12;
    int n = gid & (N_ - 1);
    const float* X = pc + (size_t)b * D_ * N_;
    float acc = 0.0f;
    #pragma unroll
    for (int d = 0; d < D_; d++) {
        float v = X[d * N_ + n];
        acc = fmaf(v, v, acc);
    }
    g_sq[gid] = acc;
}

// ---------------------------------------------------------------------------
// 2) dist = sqrt(max(sq_i + sq_j - 2*dot, 0)). UPPER-TRIANGLE tiles only
//    (528 per batch): dist(i,j) is bitwise == dist(j,i) (same FMA chains,
//    validated in an earlier round). Mainloop = proven R9 FFMA2 (plain
//    As/Bs + register mov.b64 dup). Mirror tile stored via a SMEM-STAGED
//    transpose reusing the As/Bs pool -> fully coalesced mirror stores.
// ---------------------------------------------------------------------------
#define AS(d, i) pool[(d) * 128 + (i)]
#define BS(d, i) pool[4096 + (d) * 128 + (i)]

__global__ __launch_bounds__(256, 2) void d2_kernel(const float* __restrict__ pc) {
    __shared__ float pool[8256];     // As 16KB | Bs 16KB ; reused as 64x129 stage
    __shared__ float sqa[128];
    __shared__ float sqb[128];

    int b = blockIdx.z;
    // decode linear tile id -> (by, bx) with bx >= by  (528 tiles)
    int tl = blockIdx.x;
    int by = 0;
    #pragma unroll 1
    while (tl >= 32 - by) { tl -= 32 - by; by++; }
    int bx = by + tl;

    int i0 = by * 128;
    int j0 = bx * 128;
    const float* X = pc + (size_t)b * D_ * N_;
    int t = threadIdx.x;

    if (t < 128) sqa[t]       = g_sq[b * N_ + i0 + t];
    else         sqb[t - 128] = g_sq[b * N_ + j0 + (t - 128)];

    int r = t >> 4;    // 0..15 row group
    int c = t & 15;    // 0..15 col group

    unsigned long long acc2[8][4];   // [row][col-pair]
    #pragma unroll
    for (int ii = 0; ii < 8; ii++)
        #pragma unroll
        for (int q = 0; q < 4; q++) acc2[ii][q] = 0ull;

    for (int dc = 0; dc < D_; dc += 32) {
        __syncthreads();
        for (int l = t; l < 1024; l += 256) {
            int d  = l >> 5;
            int i4 = (l & 31) << 2;
            *(float4*)&AS(d, i4) = *(const float4*)&X[(size_t)(dc + d) * N_ + i0 + i4];
            *(float4*)&BS(d, i4) = *(const float4*)&X[(size_t)(dc + d) * N_ + j0 + i4];
        }
        __syncthreads();

        #pragma unroll 8
        for (int d = 0; d < 32; d++) {
            float af[8];
            *(float4*)&af[0] = *(float4*)&AS(d, r * 8);
            *(float4*)&af[4] = *(float4*)&AS(d, r * 8 + 4);
            ulonglong2 B0 = *(const ulonglong2*)&BS(d, c * 8);
            ulonglong2 B1 = *(const ulonglong2*)&BS(d, c * 8 + 4);
            unsigned long long bp[4] = {B0.x, B0.y, B1.x, B1.y};
            unsigned long long ap[8];
            #pragma unroll
            for (int ii = 0; ii < 8; ii++)
                asm("mov.b64 %0, {%1, %1};" : "=l"(ap[ii]) : "f"(af[ii]));
            #pragma unroll
            for (int ii = 0; ii < 8; ii++)
                #pragma unroll
                for (int q = 0; q < 4; q++)
                    fma2(acc2[ii][q], ap[ii], bp[q]);
        }
    }

    // normal store: rows i0.., cols j0.. (coalesced float4)
    #pragma unroll
    for (int ii = 0; ii < 8; ii++) {
        float si = sqa[r * 8 + ii];
        float v[8];
        #pragma unroll
        for (int q = 0; q < 4; q++) {
            float dx = __uint_as_float((unsigned)acc2[ii][q]);
            float dy = __uint_as_float((unsigned)(acc2[ii][q] >> 32));
            float s0 = si + sqb[c * 8 + 2 * q];
            float s1 = si + sqb[c * 8 + 2 * q + 1];
            v[2 * q]     = sqrtf(fmaxf(s0 - 2.0f * dx, 0.0f));
            v[2 * q + 1] = sqrtf(fmaxf(s1 - 2.0f * dy, 0.0f));
        }
        float* dst = g_dist + ((size_t)(b * N_ + i0 + r * 8 + ii) << 12) + j0 + c * 8;
        *(float4*)&dst[0] = *(float4*)&v[0];
        *(float4*)&dst[4] = *(float4*)&v[4];
    }

    // mirror store via staged transpose (off-diagonal tiles only).
    // Two rounds of 64 output-rows (cc = j-offset); stage[cc][i], row pitch
    // 129 to spread banks. Values recomputed from live acc2 -> bitwise same.
    if (bx != by) {
        #pragma unroll
        for (int p = 0; p < 2; p++) {
            __syncthreads();            // pool free (mainloop/prev round done)
            if ((c >> 3) == p) {
                int cl = (c & 7) * 8;   // stage row base for this thread
                #pragma unroll
                for (int ii = 0; ii < 8; ii++) {
                    float si = sqa[r * 8 + ii];
                    #pragma unroll
                    for (int q = 0; q < 4; q++) {
                        float dx = __uint_as_float((unsigned)acc2[ii][q]);
                        float dy = __uint_as_float((unsigned)(acc2[ii][q] >> 32));
                        float s0 = si + sqb[c * 8 + 2 * q];
                        float s1 = si + sqb[c * 8 + 2 * q + 1];
                        pool[(cl + 2 * q)     * 129 + r * 8 + ii] =
                            sqrtf(fmaxf(s0 - 2.0f * dx, 0.0f));
                        pool[(cl + 2 * q + 1) * 129 + r * 8 + ii] =
                            sqrtf(fmaxf(s1 - 2.0f * dy, 0.0f));
                    }
                }
            }
            __syncthreads();
            // copy out: row j0+64p+cc, cols i0..i0+127 (coalesced)
            int jbase = j0 + p * 64;
            #pragma unroll
            for (int k = 0; k < 32; k++) {
                int idx = t + k * 256;
                int cc = idx >> 7;
                int i  = idx & 127;
                g_dist[((size_t)(b * N_ + jbase + cc) << 12) + i0 + i] =
                    pool[cc * 129 + i];
            }
        }
    }
}

// ---------------------------------------------------------------------------
// 3) select — proven R6/R8 configuration (~116us): single launch, 16384
//    blocks. Threshold-filter (warp bitonic of lane minima), one atomic per
//    warp, exact 17-pass warp argmin on u64 keys (bits<<32)|j == lax.top_k.
// ---------------------------------------------------------------------------
__global__ __launch_bounds__(256) void select_kernel(float* __restrict__ out_idx_f) {
    __shared__ unsigned long long buf[4096];
    __shared__ float wtau[8];
    __shared__ int cnt;

    int row = blockIdx.x;                      // b*4096 + i
    const float* src = g_dist + (size_t)row * N_;
    int t = threadIdx.x;
    int lane = t & 31, w = t >> 5;
    unsigned lmask_lt = (1u << lane) - 1u;

    if (t == 0) cnt = 0;

    float4 vv[4];
    #pragma unroll
    for (int u = 0; u < 4; u++)
        vv[u] = ((const float4*)src)[128 * w + lane + 32 * u];

    float mn;
    {
        float m0 = fminf(fminf(vv[0].x, vv[0].y), fminf(vv[0].z, vv[0].w));
        float m1 = fminf(fminf(vv[1].x, vv[1].y), fminf(vv[1].z, vv[1].w));
        float m2 = fminf(fminf(vv[2].x, vv[2].y), fminf(vv[2].z, vv[2].w));
        float m3 = fminf(fminf(vv[3].x, vv[3].y), fminf(vv[3].z, vv[3].w));
        mn = fminf(fminf(m0, m1), fminf(m2, m3));
    }

    float x = mn;
    #pragma unroll
    for (int k = 2; k <= 32; k <<= 1) {
        #pragma unroll
        for (int j2 = k >> 1; j2 > 0; j2 >>= 1) {
            float other = __shfl_xor_sync(0xffffffffu, x, j2);
            bool up    = ((lane & k) == 0);
            bool small = ((lane & j2) == 0);
            x = (small == up) ? fminf(x, other) : fmaxf(x, other);
        }
    }
    float tau_w = __shfl_sync(0xffffffffu, x, K_);
    if (lane == 0) wtau[w] = tau_w;
    __syncthreads();
    float tau = wtau[0];
    #pragma unroll
    for (int q = 1; q < 8; q++) tau = fminf(tau, wtau[q]);

    float    val[16];
    unsigned msk[16];
    int tot = 0;
    #pragma unroll
    for (int u = 0; u < 4; u++) {
        val[u * 4 + 0] = vv[u].x; val[u * 4 + 1] = vv[u].y;
        val[u * 4 + 2] = vv[u].z; val[u * 4 + 3] = vv[u].w;
    }
    #pragma unroll
    for (int e = 0; e < 16; e++) {
        msk[e] = __ballot_sync(0xffffffffu, val[e] <= tau);
        tot += __popc(msk[e]);
    }
    int wbase = 0;
    if (lane == 0) wbase = atomicAdd(&cnt, tot);
    wbase = __shfl_sync(0xffffffffu, wbase, 0);
    int off = 0;
    #pragma unroll
    for (int e = 0; e < 16; e++) {
        if (val[e] <= tau) {
            int j = (128 * w + lane + 32 * (e >> 2)) * 4 + (e & 3);
            buf[wbase + off + __popc(msk[e] & lmask_lt)] =
                ((unsigned long long)__float_as_uint(val[e]) << 32) | (unsigned)j;
        }
        off += __popc(msk[e]);
    }
    __syncthreads();

    if (w == 0) {
        int n = cnt;
        for (int p = 0; p <= K_; p++) {
            unsigned long long m = 0xFFFFFFFFFFFFFFFFull;
            for (int q = lane; q < n; q += 32) m = (buf[q] < m) ? buf[q] : m;
            #pragma unroll
            for (int o2 = 16; o2; o2 >>= 1) {
                unsigned long long o = __shfl_xor_sync(0xffffffffu, m, o2);
                m = (o < m) ? o : m;
            }
            for (int q = lane; q < n; q += 32)
                if (buf[q] == m) buf[q] = 0xFFFFFFFFFFFFFFFFull;
            if (lane == 0 && p > 0) {
                int j = (int)(m & 0xFFFFFFFFu);
                g_idx[row * K_ + (p - 1)]     = j;
                out_idx_f[row * K_ + (p - 1)] = (float)j;
            }
        }
    }
}

// ---------------------------------------------------------------------------
// 4) gather v3 (measured ~37us): smem-row gather. Block = (b, channel, octant).
// ---------------------------------------------------------------------------
__global__ __launch_bounds__(256) void gather_kernel(const float* __restrict__ pc,
                                                     float* __restrict__ out) {
    __shared__ float rowv[N_];

    int blk = blockIdx.x;            // 2048 blocks: b(2) | c(6) | s(3)
    int s   = blk & 7;
    int c   = (blk >> 3) & 63;
    int b   = blk >> 9;
    int t   = threadIdx.x;
    const float* src = pc + ((size_t)b * D_ + c) * N_;

    #pragma unroll
    for (int q = 0; q < 4; q++)
        ((float4*)rowv)[t + q * 256] = ((const float4*)src)[t + q * 256];
    __syncthreads();

    int n0 = s * 512;
    const int* idxp = g_idx + ((size_t)b * N_ + n0) * K_;
    size_t obase = (size_t)b * 2 * D_ * N_ * K_ + ((size_t)c * N_ + n0) * K_;
    float* oc = out + obase;
    float* on = out + obase + (size_t)D_ * N_ * K_;

    #pragma unroll 4
    for (int it = 0; it < 32; it++) {
        int l = t + it * 256;
        int n = l >> 4;
        int j = idxp[l];
        float ce = rowv[n0 + n];
        float nb = rowv[j];
        oc[l] = ce;
        on[l] = nb - ce;
    }
}

// ---------------------------------------------------------------------------
extern "C" void kernel_launch(void* const* d_in, const int* in_sizes, int n_in,
                              void* d_out, int out_size) {
    const float* pc = (const float*)d_in[0];
    float* out = (float*)d_out;
    float* out_idx = out + (size_t)B_ * 2 * D_ * N_ * K_;

    sq_kernel<<<(B_ * N_) / 256, 256>>>(pc);
    dim3 gg(528, 1, B_);                      // upper-triangle tiles
    d2_kernel<<<gg, 256>>>(pc);
    select_kernel<<<B_ * N_, 256>>>(out_idx);
    gather_kernel<<<B_ * D_ * 8, 256>>>(pc, out);
}